// round 1
// baseline (speedup 1.0000x reference)
#include <cuda_runtime.h>

#define BATCH 8
#define CH 128
#define HH 128
#define WW 128
#define KW 9
#define PW 4

// fp32 working state in (b, i, j, c) layout. 64 MB static device array
// (allocation-free scratch, per harness rules).
__device__ float g_y[BATCH * HH * WW * CH];

typedef unsigned long long u64;

__device__ __forceinline__ u64 pack2(float x) {
    u64 r;
    asm("mov.b64 %0, {%1, %1};" : "=l"(r) : "f"(x));
    return r;
}
__device__ __forceinline__ void fma2(u64& d, u64 a, u64 b) {
    asm("fma.rn.f32x2 %0, %1, %2, %0;" : "+l"(d) : "l"(a), "l"(b));
}
__device__ __forceinline__ float2 unpack2(u64 v) {
    float2 f;
    asm("mov.b64 {%0, %1}, %2;" : "=f"(f.x), "=f"(f.y) : "l"(v));
    return f;
}

// ---------------------------------------------------------------------------
// Transpose in: x (B,C,H,W) -> g_y (B,H,W,C)
// ---------------------------------------------------------------------------
__global__ void t_in_kernel(const float* __restrict__ x) {
    __shared__ float tile[32][33];
    int b = blockIdx.z >> 7;
    int h = blockIdx.z & 127;
    int w0 = blockIdx.x * 32;
    int c0 = blockIdx.y * 32;
    int tx = threadIdx.x, ty = threadIdx.y;
#pragma unroll
    for (int k = 0; k < 32; k += 8) {
        int c = c0 + ty + k;
        tile[ty + k][tx] = x[(((b * CH + c) * HH + h) * WW) + w0 + tx];
    }
    __syncthreads();
#pragma unroll
    for (int k = 0; k < 32; k += 8) {
        int w = w0 + ty + k;
        g_y[(((b * HH + h) * WW + w) * CH) + c0 + tx] = tile[tx][ty + k];
    }
}

// ---------------------------------------------------------------------------
// Transpose out: g_y (B,H,W,C) -> out (B,C,H,W)
// ---------------------------------------------------------------------------
__global__ void t_out_kernel(float* __restrict__ o) {
    __shared__ float tile[32][33];
    int b = blockIdx.z >> 7;
    int h = blockIdx.z & 127;
    int w0 = blockIdx.x * 32;
    int c0 = blockIdx.y * 32;
    int tx = threadIdx.x, ty = threadIdx.y;
#pragma unroll
    for (int k = 0; k < 32; k += 8) {
        int w = w0 + ty + k;
        tile[ty + k][tx] = g_y[(((b * HH + h) * WW + w) * CH) + c0 + tx];
    }
    __syncthreads();
#pragma unroll
    for (int k = 0; k < 32; k += 8) {
        int c = c0 + ty + k;
        o[(((b * CH + c) * HH + h) * WW) + w0 + tx] = tile[tx][ty + k];
    }
}

// ---------------------------------------------------------------------------
// One scan step (in-place):
//   y[cur][m][co] += relu( sum_{t,ci} y[prev][m+t-4][ci] * K[t][ci][co] )
// stride_m: element stride along the conv axis (128 for H-scan rows,
// 16384 for W-scan columns). cur_off / prev_off: element offsets of the
// current / previous scan position within one batch image.
// Grid: (4 m-tiles, 4 co-tiles, 8 batches), 128 threads.
// Thread computes 2 m-positions x 4 output channels using packed f32x2 FMA.
// ---------------------------------------------------------------------------
__global__ void __launch_bounds__(128) step_kernel(
    const float* __restrict__ Kw, int cur_off, int prev_off, int stride_m) {
    __shared__ float sp[40][132];  // prev rows mt-4 .. mt+35, padded rows

    int tid = threadIdx.x;
    int b = blockIdx.z;
    int mt = blockIdx.x * 32;
    int co0 = blockIdx.y * 32;
    const float* prow = g_y + (size_t)b * (HH * WW * CH) + prev_off;

    // Stage prev rows with halo into SMEM (zero-padded at boundaries).
#pragma unroll
    for (int ch = 0; ch < 10; ch++) {
        int lin = ch * 512 + tid * 4;
        int r = lin >> 7;
        int ci = lin & 127;
        int row = mt - 4 + r;
        float4 v = make_float4(0.f, 0.f, 0.f, 0.f);
        if (row >= 0 && row < HH)
            v = *(const float4*)(prow + (size_t)row * stride_m + ci);
        *(float4*)(&sp[r][ci]) = v;
    }
    __syncthreads();

    int cg = tid & 7;        // co group: 4 channels
    int mp = tid >> 3;       // 0..15
    int m0 = mp, m1 = mp + 16;
    const float* kb = Kw + co0 + cg * 4;

    u64 a00 = 0, a01 = 0, a10 = 0, a11 = 0;

    for (int t = 0; t < KW; t++) {
        const float* kt = kb + t * (CH * CH);
        const float* s0 = &sp[m0 + t][0];
        const float* s1 = &sp[m1 + t][0];
#pragma unroll 4
        for (int ci = 0; ci < CH; ci++) {
            u64 p0 = pack2(s0[ci]);
            u64 p1 = pack2(s1[ci]);
            ulonglong2 w = *(const ulonglong2*)(kt + ci * CH);
            fma2(a00, p0, w.x);
            fma2(a01, p0, w.y);
            fma2(a10, p1, w.x);
            fma2(a11, p1, w.y);
        }
    }

    float* crow = g_y + (size_t)b * (HH * WW * CH) + cur_off;
    float2 r00 = unpack2(a00), r01 = unpack2(a01);
    float2 r10 = unpack2(a10), r11 = unpack2(a11);

    {
        float4* o0 = (float4*)(crow + (size_t)(mt + m0) * stride_m + co0 + cg * 4);
        float4 c = *o0;
        c.x += fmaxf(r00.x, 0.f);
        c.y += fmaxf(r00.y, 0.f);
        c.z += fmaxf(r01.x, 0.f);
        c.w += fmaxf(r01.y, 0.f);
        *o0 = c;
    }
    {
        float4* o1 = (float4*)(crow + (size_t)(mt + m1) * stride_m + co0 + cg * 4);
        float4 c = *o1;
        c.x += fmaxf(r10.x, 0.f);
        c.y += fmaxf(r10.y, 0.f);
        c.z += fmaxf(r11.x, 0.f);
        c.w += fmaxf(r11.y, 0.f);
        *o1 = c;
    }
}

// ---------------------------------------------------------------------------
extern "C" void kernel_launch(void* const* d_in, const int* in_sizes, int n_in,
                              void* d_out, int out_size) {
    const float* x   = (const float*)d_in[0];
    const float* ktd = (const float*)d_in[1];
    const float* kdt = (const float*)d_in[2];
    const float* klr = (const float*)d_in[3];
    const float* krl = (const float*)d_in[4];

    dim3 tb(32, 8);
    dim3 tg(WW / 32, CH / 32, BATCH * HH);
    t_in_kernel<<<tg, tb>>>(x);

    dim3 sg(4, 4, BATCH);
    const int ROW = WW * CH;  // 16384

    // Top-down: scan i, conv along j (stride_m = CH)
    for (int p = 1; p < HH; p++)
        step_kernel<<<sg, 128>>>(ktd, p * ROW, (p - 1) * ROW, CH);
    // Bottom-up
    for (int p = HH - 2; p >= 0; p--)
        step_kernel<<<sg, 128>>>(kdt, p * ROW, (p + 1) * ROW, CH);
    // Left-right: scan j, conv along i (stride_m = W*C)
    for (int p = 1; p < WW; p++)
        step_kernel<<<sg, 128>>>(klr, p * CH, (p - 1) * CH, ROW);
    // Right-left
    for (int p = WW - 2; p >= 0; p--)
        step_kernel<<<sg, 128>>>(krl, p * CH, (p + 1) * CH, ROW);

    t_out_kernel<<<tg, tb>>>((float*)d_out);
}